// round 7
// baseline (speedup 1.0000x reference)
#include <cuda_runtime.h>

#define DIM 16

// Folded weights: out = chem @ M^T + c, where M = Wo @ Wv, c = Wo @ bv + bo
__device__ __align__(16) float g_M[DIM * DIM];  // M[j][i], row-major
__device__ __align__(16) float g_c[DIM];

// ---------------------------------------------------------------------------
// Tiny prep kernel: fold the two 16x16 matmuls + biases into one matrix.
// One block, 256 threads: thread (j,i) computes M[j][i].
// ---------------------------------------------------------------------------
__global__ void prep_kernel(const float* __restrict__ in_w,   // [48,16] (Wq|Wk|Wv)
                            const float* __restrict__ in_b,   // [48]
                            const float* __restrict__ out_w,  // [16,16]
                            const float* __restrict__ out_b)  // [16]
{
    const int t = threadIdx.x;           // 0..255
    const int j = t >> 4;
    const int i = t & 15;
    float s = 0.f;
#pragma unroll
    for (int k = 0; k < DIM; ++k)
        s += out_w[j * DIM + k] * in_w[(2 * DIM + k) * DIM + i];
    g_M[j * DIM + i] = s;
    if (i == 0) {
        float c = out_b[j];
#pragma unroll
        for (int k = 0; k < DIM; ++k)
            c += out_w[j * DIM + k] * in_b[2 * DIM + k];
        g_c[j] = c;
    }
}

// packed f32x2 FMA (Blackwell; only reachable via PTX)
__device__ __forceinline__ unsigned long long ffma2(unsigned long long a,
                                                    unsigned long long b,
                                                    unsigned long long c)
{
    unsigned long long d;
    asm("fma.rn.f32x2 %0, %1, %2, %3;" : "=l"(d) : "l"(a), "l"(b), "l"(c));
    return d;
}

// ---------------------------------------------------------------------------
// Main kernel: 4 threads per row, 4 output columns per thread, TWO
// consecutive rows per iteration. Each thread's 8 LDG.128 cover 128
// contiguous bytes and are issued back-to-back before any compute, doubling
// in-flight memory vs the 1-row version. Weights (64 regs) are shared
// across both rows, so the register cost of batching is only the extra
// input registers.
// ---------------------------------------------------------------------------
__global__ void __launch_bounds__(256)
matvec_kernel(const float* __restrict__ chem, float* __restrict__ out, int rows)
{
    const int g       = blockIdx.x * blockDim.x + threadIdx.x;
    const int quarter = g & 3;            // which 4-column group of the row
    const int jg      = quarter * 4;      // first output column
    const int pair0   = g >> 2;           // row-pair index
    const int pstride = (gridDim.x * blockDim.x) >> 2;
    const int npairs  = rows >> 1;        // rows is even (2^21)

    // Load this thread's 4 rows of M (64 weights) as 32 packed f32x2 regs.
    unsigned long long w[4][8];
    float c[4];
#pragma unroll
    for (int j = 0; j < 4; ++j) {
        const unsigned long long* wp =
            reinterpret_cast<const unsigned long long*>(&g_M[(jg + j) * DIM]);
#pragma unroll
        for (int i2 = 0; i2 < 8; ++i2) w[j][i2] = wp[i2];
        c[j] = g_c[jg + j];
    }

    for (int pr = pair0; pr < npairs; pr += pstride) {
        const size_t r = (size_t)pr * 2;
        const ulonglong2* p =
            reinterpret_cast<const ulonglong2*>(chem + r * DIM);
        // 8 back-to-back LDG.128 covering 128 contiguous bytes (2 rows)
        ulonglong2 a0 = p[0];
        ulonglong2 a1 = p[1];
        ulonglong2 a2 = p[2];
        ulonglong2 a3 = p[3];
        ulonglong2 a4 = p[4];
        ulonglong2 a5 = p[5];
        ulonglong2 a6 = p[6];
        ulonglong2 a7 = p[7];

        const unsigned long long apA[8] = {a0.x, a0.y, a1.x, a1.y,
                                           a2.x, a2.y, a3.x, a3.y};
        const unsigned long long apB[8] = {a4.x, a4.y, a5.x, a5.y,
                                           a6.x, a6.y, a7.x, a7.y};

        float4 resA, resB;
        float* rpA = reinterpret_cast<float*>(&resA);
        float* rpB = reinterpret_cast<float*>(&resB);
#pragma unroll
        for (int j = 0; j < 4; ++j) {
            unsigned long long accA =
                (unsigned long long)__float_as_uint(c[j]);
            unsigned long long accB =
                (unsigned long long)__float_as_uint(c[j]);
#pragma unroll
            for (int i2 = 0; i2 < 8; ++i2) {
                accA = ffma2(apA[i2], w[j][i2], accA);
                accB = ffma2(apB[i2], w[j][i2], accB);
            }
            rpA[j] = __uint_as_float((unsigned int)accA) +
                     __uint_as_float((unsigned int)(accA >> 32));
            rpB[j] = __uint_as_float((unsigned int)accB) +
                     __uint_as_float((unsigned int)(accB >> 32));
        }

        // two coalesced 16B stores per thread; 4 threads cover each row
        float4* opA = reinterpret_cast<float4*>(out + r * DIM);
        float4* opB = reinterpret_cast<float4*>(out + (r + 1) * DIM);
        opA[quarter] = resA;
        opB[quarter] = resB;
    }
}

extern "C" void kernel_launch(void* const* d_in, const int* in_sizes, int n_in,
                              void* d_out, int out_size)
{
    // inputs: 0=fp_16 (UNUSED), 1=chem_16, 2=in_proj_weight, 3=in_proj_bias,
    //         4=out_proj_weight, 5=out_proj_bias
    const float* chem  = (const float*)d_in[1];
    const float* in_w  = (const float*)d_in[2];
    const float* in_b  = (const float*)d_in[3];
    const float* out_w = (const float*)d_in[4];
    const float* out_b = (const float*)d_in[5];
    float* out = (float*)d_out;

    const int rows = in_sizes[1] / DIM;   // 2,097,152

    prep_kernel<<<1, 256>>>(in_w, in_b, out_w, out_b);

    // 2048 blocks x 256 threads; each thread handles (rows/2)/2^17 = 8 pairs
    int blocks = 2048;
    long long need = ((long long)(rows >> 1) * 4 + 255) / 256;
    if (need < blocks) blocks = (int)need;
    matvec_kernel<<<blocks, 256>>>(chem, out, rows);
}

// round 9
// speedup vs baseline: 1.4142x; 1.4142x over previous
#include <cuda_runtime.h>

#define DIM 16

// Folded weights: out = chem @ M^T + c, where M = Wo @ Wv, c = Wo @ bv + bo
__device__ __align__(16) float g_M[DIM * DIM];  // M[j][i], row-major
__device__ __align__(16) float g_c[DIM];

// ---------------------------------------------------------------------------
// Tiny prep kernel: fold the two 16x16 matmuls + biases into one matrix.
// One block, 256 threads: thread (j,i) computes M[j][i].
// ---------------------------------------------------------------------------
__global__ void prep_kernel(const float* __restrict__ in_w,   // [48,16] (Wq|Wk|Wv)
                            const float* __restrict__ in_b,   // [48]
                            const float* __restrict__ out_w,  // [16,16]
                            const float* __restrict__ out_b)  // [16]
{
    const int t = threadIdx.x;           // 0..255
    const int j = t >> 4;
    const int i = t & 15;
    float s = 0.f;
#pragma unroll
    for (int k = 0; k < DIM; ++k)
        s += out_w[j * DIM + k] * in_w[(2 * DIM + k) * DIM + i];
    g_M[j * DIM + i] = s;
    if (i == 0) {
        float c = out_b[j];
#pragma unroll
        for (int k = 0; k < DIM; ++k)
            c += out_w[j * DIM + k] * in_b[2 * DIM + k];
        g_c[j] = c;
    }
}

// packed f32x2 FMA (Blackwell; only reachable via PTX)
__device__ __forceinline__ unsigned long long ffma2(unsigned long long a,
                                                    unsigned long long b,
                                                    unsigned long long c)
{
    unsigned long long d;
    asm("fma.rn.f32x2 %0, %1, %2, %3;" : "=l"(d) : "l"(a), "l"(b), "l"(c));
    return d;
}

// ---------------------------------------------------------------------------
// Main kernel: 8 threads per row (2 output columns each), FOUR consecutive
// rows per thread-batch. Weight footprint is only 16 packed pairs (32 regs),
// so the 16 back-to-back LDG.128 (256 contiguous bytes) fit under the
// 128-reg / 2-blocks-per-SM line. In-flight unique bytes per SM:
// 16 warps x 16 rows x 64B = 16KB (2x the best previous kernel).
// ---------------------------------------------------------------------------
__global__ void __launch_bounds__(256, 2)
matvec_kernel(const float* __restrict__ chem, float* __restrict__ out, int rows)
{
    const int g      = blockIdx.x * blockDim.x + threadIdx.x;
    const int e      = g & 7;             // which 2-column group of the row
    const int jg     = e * 2;             // first output column
    const int qstride = (gridDim.x * blockDim.x) >> 3;   // quad-groups
    const int nquads = rows >> 2;         // rows is 2^21, divisible by 4

    // This thread's 2 rows of M as 16 packed f32x2 regs.
    unsigned long long w0[8], w1[8];
    {
        const unsigned long long* wp0 =
            reinterpret_cast<const unsigned long long*>(&g_M[(jg + 0) * DIM]);
        const unsigned long long* wp1 =
            reinterpret_cast<const unsigned long long*>(&g_M[(jg + 1) * DIM]);
#pragma unroll
        for (int i2 = 0; i2 < 8; ++i2) { w0[i2] = wp0[i2]; w1[i2] = wp1[i2]; }
    }
    const float c0 = g_c[jg + 0];
    const float c1 = g_c[jg + 1];

    for (int q = g >> 3; q < nquads; q += qstride) {
        // 16 back-to-back LDG.128 covering 4 consecutive rows (256B)
        const ulonglong2* p =
            reinterpret_cast<const ulonglong2*>(chem + (size_t)q * (4 * DIM));
        ulonglong2 a[16];
#pragma unroll
        for (int i = 0; i < 16; ++i) a[i] = p[i];

#pragma unroll
        for (int k = 0; k < 4; ++k) {
            const unsigned long long ap[8] = {
                a[4 * k + 0].x, a[4 * k + 0].y,
                a[4 * k + 1].x, a[4 * k + 1].y,
                a[4 * k + 2].x, a[4 * k + 2].y,
                a[4 * k + 3].x, a[4 * k + 3].y};

            unsigned long long acc0 =
                (unsigned long long)__float_as_uint(c0);
            unsigned long long acc1 =
                (unsigned long long)__float_as_uint(c1);
#pragma unroll
            for (int i2 = 0; i2 < 8; ++i2) {
                acc0 = ffma2(ap[i2], w0[i2], acc0);
                acc1 = ffma2(ap[i2], w1[i2], acc1);
            }
            float2 res;
            res.x = __uint_as_float((unsigned int)acc0) +
                    __uint_as_float((unsigned int)(acc0 >> 32));
            res.y = __uint_as_float((unsigned int)acc1) +
                    __uint_as_float((unsigned int)(acc1 >> 32));

            // 8 threads cover each row; warp store = 256B across 4 rows
            reinterpret_cast<float2*>(
                out + ((size_t)q * 4 + k) * DIM)[e] = res;
        }
    }
}

extern "C" void kernel_launch(void* const* d_in, const int* in_sizes, int n_in,
                              void* d_out, int out_size)
{
    // inputs: 0=fp_16 (UNUSED), 1=chem_16, 2=in_proj_weight, 3=in_proj_bias,
    //         4=out_proj_weight, 5=out_proj_bias
    const float* chem  = (const float*)d_in[1];
    const float* in_w  = (const float*)d_in[2];
    const float* in_b  = (const float*)d_in[3];
    const float* out_w = (const float*)d_in[4];
    const float* out_b = (const float*)d_in[5];
    float* out = (float*)d_out;

    const int rows = in_sizes[1] / DIM;   // 2,097,152

    prep_kernel<<<1, 256>>>(in_w, in_b, out_w, out_b);

    // 2048 blocks x 256 threads = 65,536 quad-slots -> 8 grid-stride iters
    int blocks = 2048;
    long long need = ((long long)(rows >> 2) * 8 + 255) / 256;
    if (need < blocks) blocks = (int)need;
    matvec_kernel<<<blocks, 256>>>(chem, out, rows);
}

// round 10
// speedup vs baseline: 1.4601x; 1.0325x over previous
#include <cuda_runtime.h>

#define DIM 16

// Folded weights: out = chem @ M^T + c, where M = Wo @ Wv, c = Wo @ bv + bo
__device__ __align__(16) float g_M[DIM * DIM];  // M[j][i], row-major
__device__ __align__(16) float g_c[DIM];

// ---------------------------------------------------------------------------
// Tiny prep kernel: fold the two 16x16 matmuls + biases into one matrix.
// One block, 256 threads: thread (j,i) computes M[j][i].
// ---------------------------------------------------------------------------
__global__ void prep_kernel(const float* __restrict__ in_w,   // [48,16] (Wq|Wk|Wv)
                            const float* __restrict__ in_b,   // [48]
                            const float* __restrict__ out_w,  // [16,16]
                            const float* __restrict__ out_b)  // [16]
{
    const int t = threadIdx.x;           // 0..255
    const int j = t >> 4;
    const int i = t & 15;
    float s = 0.f;
#pragma unroll
    for (int k = 0; k < DIM; ++k)
        s += out_w[j * DIM + k] * in_w[(2 * DIM + k) * DIM + i];
    g_M[j * DIM + i] = s;
    if (i == 0) {
        float c = out_b[j];
#pragma unroll
        for (int k = 0; k < DIM; ++k)
            c += out_w[j * DIM + k] * in_b[2 * DIM + k];
        g_c[j] = c;
    }
}

// packed f32x2 FMA (Blackwell; only reachable via PTX)
__device__ __forceinline__ unsigned long long ffma2(unsigned long long a,
                                                    unsigned long long b,
                                                    unsigned long long c)
{
    unsigned long long d;
    asm("fma.rn.f32x2 %0, %1, %2, %3;" : "=l"(d) : "l"(a), "l"(b), "l"(c));
    return d;
}

// ---------------------------------------------------------------------------
// Main kernel: 8 threads per row (2 output columns each), FOUR consecutive
// rows per thread-batch. Weight footprint is only 16 packed pairs (32 regs),
// so the 16 back-to-back LDG.128 (256 contiguous bytes) fit under the
// 128-reg / 2-blocks-per-SM line. In-flight unique bytes per SM:
// 16 warps x 16 rows x 64B = 16KB (2x the best previous kernel).
// ---------------------------------------------------------------------------
__global__ void __launch_bounds__(256, 2)
matvec_kernel(const float* __restrict__ chem, float* __restrict__ out, int rows)
{
    const int g      = blockIdx.x * blockDim.x + threadIdx.x;
    const int e      = g & 7;             // which 2-column group of the row
    const int jg     = e * 2;             // first output column
    const int qstride = (gridDim.x * blockDim.x) >> 3;   // quad-groups
    const int nquads = rows >> 2;         // rows is 2^21, divisible by 4

    // This thread's 2 rows of M as 16 packed f32x2 regs.
    unsigned long long w0[8], w1[8];
    {
        const unsigned long long* wp0 =
            reinterpret_cast<const unsigned long long*>(&g_M[(jg + 0) * DIM]);
        const unsigned long long* wp1 =
            reinterpret_cast<const unsigned long long*>(&g_M[(jg + 1) * DIM]);
#pragma unroll
        for (int i2 = 0; i2 < 8; ++i2) { w0[i2] = wp0[i2]; w1[i2] = wp1[i2]; }
    }
    const float c0 = g_c[jg + 0];
    const float c1 = g_c[jg + 1];

    for (int q = g >> 3; q < nquads; q += qstride) {
        // 16 back-to-back LDG.128 covering 4 consecutive rows (256B)
        const ulonglong2* p =
            reinterpret_cast<const ulonglong2*>(chem + (size_t)q * (4 * DIM));
        ulonglong2 a[16];
#pragma unroll
        for (int i = 0; i < 16; ++i) a[i] = p[i];

#pragma unroll
        for (int k = 0; k < 4; ++k) {
            const unsigned long long ap[8] = {
                a[4 * k + 0].x, a[4 * k + 0].y,
                a[4 * k + 1].x, a[4 * k + 1].y,
                a[4 * k + 2].x, a[4 * k + 2].y,
                a[4 * k + 3].x, a[4 * k + 3].y};

            unsigned long long acc0 =
                (unsigned long long)__float_as_uint(c0);
            unsigned long long acc1 =
                (unsigned long long)__float_as_uint(c1);
#pragma unroll
            for (int i2 = 0; i2 < 8; ++i2) {
                acc0 = ffma2(ap[i2], w0[i2], acc0);
                acc1 = ffma2(ap[i2], w1[i2], acc1);
            }
            float2 res;
            res.x = __uint_as_float((unsigned int)acc0) +
                    __uint_as_float((unsigned int)(acc0 >> 32));
            res.y = __uint_as_float((unsigned int)acc1) +
                    __uint_as_float((unsigned int)(acc1 >> 32));

            // 8 threads cover each row; warp store = 256B across 4 rows
            reinterpret_cast<float2*>(
                out + ((size_t)q * 4 + k) * DIM)[e] = res;
        }
    }
}

extern "C" void kernel_launch(void* const* d_in, const int* in_sizes, int n_in,
                              void* d_out, int out_size)
{
    // inputs: 0=fp_16 (UNUSED), 1=chem_16, 2=in_proj_weight, 3=in_proj_bias,
    //         4=out_proj_weight, 5=out_proj_bias
    const float* chem  = (const float*)d_in[1];
    const float* in_w  = (const float*)d_in[2];
    const float* in_b  = (const float*)d_in[3];
    const float* out_w = (const float*)d_in[4];
    const float* out_b = (const float*)d_in[5];
    float* out = (float*)d_out;

    const int rows = in_sizes[1] / DIM;   // 2,097,152

    prep_kernel<<<1, 256>>>(in_w, in_b, out_w, out_b);

    // 2048 blocks x 256 threads = 65,536 quad-slots -> 8 grid-stride iters
    int blocks = 2048;
    long long need = ((long long)(rows >> 2) * 8 + 255) / 256;
    if (need < blocks) blocks = (int)need;
    matvec_kernel<<<blocks, 256>>>(chem, out, rows);
}

// round 11
// speedup vs baseline: 1.5801x; 1.0822x over previous
#include <cuda_runtime.h>

#define DIM 16
#define TILE_ROWS 512
#define ROW_WORDS 20            /* 16 data floats + 4 pad -> 80B row stride */
#define TILE_WORDS (TILE_ROWS * ROW_WORDS)

// Folded weights: out = chem @ M^T + c, where M = Wo @ Wv, c = Wo @ bv + bo
__device__ __align__(16) float g_M[DIM * DIM];  // M[j][i], row-major
__device__ __align__(16) float g_c[DIM];

// ---------------------------------------------------------------------------
// Tiny prep kernel: fold the two 16x16 matmuls + biases into one matrix.
// ---------------------------------------------------------------------------
__global__ void prep_kernel(const float* __restrict__ in_w,   // [48,16]
                            const float* __restrict__ in_b,   // [48]
                            const float* __restrict__ out_w,  // [16,16]
                            const float* __restrict__ out_b)  // [16]
{
    const int t = threadIdx.x;           // 0..255
    const int j = t >> 4;
    const int i = t & 15;
    float s = 0.f;
#pragma unroll
    for (int k = 0; k < DIM; ++k)
        s += out_w[j * DIM + k] * in_w[(2 * DIM + k) * DIM + i];
    g_M[j * DIM + i] = s;
    if (i == 0) {
        float c = out_b[j];
#pragma unroll
        for (int k = 0; k < DIM; ++k)
            c += out_w[j * DIM + k] * in_b[2 * DIM + k];
        g_c[j] = c;
    }
}

// packed f32x2 FMA (Blackwell; only reachable via PTX)
__device__ __forceinline__ unsigned long long ffma2(unsigned long long a,
                                                    unsigned long long b,
                                                    unsigned long long c)
{
    unsigned long long d;
    asm("fma.rn.f32x2 %0, %1, %2, %3;" : "=l"(d) : "l"(a), "l"(b), "l"(c));
    return d;
}

// ---------------------------------------------------------------------------
// Two-phase tile kernel.
//  Phase 1: cp.async.cg stages a 512-row tile (32KB of data) into smem with
//           perfectly coalesced 512B-per-warp-instruction loads (128B/wf).
//           Rows are padded to 80B so the compute phase is bank-conflict-free.
//  Phase 2: 4 threads/row x 4 output cols/thread (weights in 64 regs),
//           inputs read from smem (broadcast within each 4-lane group, the
//           8 row addresses per warp hit 8 distinct bank groups).
// ---------------------------------------------------------------------------
__global__ void __launch_bounds__(256, 2)
matvec_kernel(const float* __restrict__ chem, float* __restrict__ out, int rows)
{
    __shared__ __align__(16) float tile[TILE_WORDS];

    const int tid = threadIdx.x;
    const size_t row_base = (size_t)blockIdx.x * TILE_ROWS;

    // ---- Phase 1: stage tile into smem via cp.async ----
    {
        const char* gbase =
            reinterpret_cast<const char*>(chem + row_base * DIM);
#pragma unroll
        for (int k = 0; k < 8; ++k) {
            const int c   = tid + k * 256;        // 16B chunk index, 0..2047
            const int r   = c >> 2;               // row within tile
            const int sub = c & 3;                // 16B chunk within row
            const unsigned smem_addr = (unsigned)
                __cvta_generic_to_shared(&tile[r * ROW_WORDS + sub * 4]);
            const char* gptr = gbase + (size_t)c * 16;
            asm volatile("cp.async.cg.shared.global [%0], [%1], 16;\n"
                         :: "r"(smem_addr), "l"(gptr));
        }
        asm volatile("cp.async.commit_group;\n");
    }

    // ---- Load weights while the tile is in flight ----
    const int e  = tid & 3;            // 4 threads per row
    const int jg = e * 4;              // first of this thread's 4 output cols
    unsigned long long w[4][8];
    float c4[4];
#pragma unroll
    for (int j = 0; j < 4; ++j) {
        const unsigned long long* wp =
            reinterpret_cast<const unsigned long long*>(&g_M[(jg + j) * DIM]);
#pragma unroll
        for (int i2 = 0; i2 < 8; ++i2) w[j][i2] = wp[i2];
        c4[j] = g_c[jg + j];
    }

    asm volatile("cp.async.wait_group 0;\n");
    __syncthreads();

    // ---- Phase 2: compute. 64 rows per pass, 8 passes cover 512 rows ----
    const int r0 = tid >> 2;           // this thread's row within the pass
#pragma unroll
    for (int p = 0; p < 8; ++p) {
        const int r = r0 + p * 64;
        const ulonglong2* sp =
            reinterpret_cast<const ulonglong2*>(&tile[r * ROW_WORDS]);
        ulonglong2 a0 = sp[0];
        ulonglong2 a1 = sp[1];
        ulonglong2 a2 = sp[2];
        ulonglong2 a3 = sp[3];
        const unsigned long long ap[8] = {a0.x, a0.y, a1.x, a1.y,
                                          a2.x, a2.y, a3.x, a3.y};

        float4 res;
        float* rp = reinterpret_cast<float*>(&res);
#pragma unroll
        for (int j = 0; j < 4; ++j) {
            unsigned long long acc =
                (unsigned long long)__float_as_uint(c4[j]);
#pragma unroll
            for (int i2 = 0; i2 < 8; ++i2)
                acc = ffma2(ap[i2], w[j][i2], acc);
            rp[j] = __uint_as_float((unsigned int)acc) +
                    __uint_as_float((unsigned int)(acc >> 32));
        }

        // warp store: lanes cover 8 consecutive rows x 64B = 512B contiguous
        reinterpret_cast<float4*>(out + (row_base + r) * DIM)[e] = res;
    }
}

extern "C" void kernel_launch(void* const* d_in, const int* in_sizes, int n_in,
                              void* d_out, int out_size)
{
    // inputs: 0=fp_16 (UNUSED), 1=chem_16, 2=in_proj_weight, 3=in_proj_bias,
    //         4=out_proj_weight, 5=out_proj_bias
    const float* chem  = (const float*)d_in[1];
    const float* in_w  = (const float*)d_in[2];
    const float* in_b  = (const float*)d_in[3];
    const float* out_w = (const float*)d_in[4];
    const float* out_b = (const float*)d_in[5];
    float* out = (float*)d_out;

    const int rows = in_sizes[1] / DIM;   // 2,097,152 (divisible by 512)

    prep_kernel<<<1, 256>>>(in_w, in_b, out_w, out_b);

    const int blocks = rows / TILE_ROWS;  // 4096 one-tile blocks
    matvec_kernel<<<blocks, 256>>>(chem, out, rows);
}